// round 4
// baseline (speedup 1.0000x reference)
#include <cuda_runtime.h>
#include <cstdint>

// Problem constants
#define BATCH 128
#define SEQ   512
#define HID   512
#define DIM   1024            // 2*HID
#define MROWS (BATCH*SEQ)     // 65536

// Scratch (no device allocation allowed -> __device__ globals)
__device__ float g_dec[BATCH * DIM];     // dec_feat = s_t @ Ws^T + b   (B, D)
__device__ float g_score[BATCH * SEQ];   // attention logits             (B, S)

// ---------------------------------------------------------------------------
// packed f32x2 helpers (B300: doubles fp32 FMA throughput vs scalar FFMA)
// ---------------------------------------------------------------------------
__device__ __forceinline__ void fma2(unsigned long long& c,
                                     unsigned long long a,
                                     unsigned long long b) {
    asm("fma.rn.f32x2 %0, %1, %2, %3;" : "=l"(c) : "l"(a), "l"(b), "l"(c));
}
__device__ __forceinline__ unsigned long long dup2(float x) {
    unsigned long long r;
    unsigned int u = __float_as_uint(x);
    asm("mov.b64 %0, {%1, %1};" : "=l"(r) : "r"(u));
    return r;
}
__device__ __forceinline__ float lo32(unsigned long long v) {
    return __uint_as_float((unsigned int)v);
}
__device__ __forceinline__ float hi32(unsigned long long v) {
    return __uint_as_float((unsigned int)(v >> 32));
}

// ---------------------------------------------------------------------------
// K1: dec_feat[b,e] = sum_d s_t[b,d] * Ws[e,d] + Ws_b[e]
//     s_t[b,d] = d<512 ? h_dec[b,d] : c_dec[b,d-512]
// grid (8, 128) : blockIdx.x = e-tile of 128, blockIdx.y = b ; 128 threads
// ---------------------------------------------------------------------------
__global__ void dec_feat_kernel(const float* __restrict__ h,
                                const float* __restrict__ c,
                                const float* __restrict__ Ws,
                                const float* __restrict__ Wsb) {
    __shared__ float st[DIM];
    const int b = blockIdx.y;
    const int e = blockIdx.x * 128 + threadIdx.x;

    for (int d = threadIdx.x; d < DIM; d += 128)
        st[d] = (d < HID) ? h[b * HID + d] : c[b * HID + d - HID];
    __syncthreads();

    const float* wrow = Ws + (size_t)e * DIM;
    float acc = Wsb[e];
#pragma unroll 8
    for (int d = 0; d < DIM; d++)
        acc = fmaf(st[d], wrow[d], acc);
    g_dec[b * DIM + e] = acc;
}

// ---------------------------------------------------------------------------
// K2: fused  score[b,s] = sum_e v[e] * tanh( (enc @ Wh^T)[row,e]
//                                            + dec_feat[b,e] + cov[b,s]*wc[e] )
// 137 GFLOP GEMM, fused epilogue (enc_feat never materialized).
// Tile: 128 rows x 128 cols, BK=16, 256 threads, 8x8 microtile as 8x4 f32x2.
// Each block covers ALL 1024 e-columns (8 chunks) -> writes score directly.
// ---------------------------------------------------------------------------
#define BM 128
#define BN 128
#define BK 16

__global__ __launch_bounds__(256)
void score_kernel(const float* __restrict__ enc,
                  const float* __restrict__ Wh,
                  const float* __restrict__ cov,
                  const float* __restrict__ v,
                  const float* __restrict__ wc) {
    __shared__ __align__(16) float As[BK][BM];   // 8 KB, stored [k][m]
    __shared__ __align__(16) float Bs[BK][BN];   // 8 KB, stored [k][n]

    const int tid = threadIdx.x;
    const int tx = tid & 15;          // 16 n-groups
    const int ty = tid >> 4;          // 16 m-groups
    const int row0 = blockIdx.x * BM;

    // rows of a block never cross a batch boundary (128 | 512)
    const int b = row0 >> 9;
    const int sbase = (row0 & 511) + ty * 8;

    // load mapping: 64 rows x 16 cols per pass, two passes
    const int lr = tid >> 2;
    const int lc = (tid & 3) << 2;

    float rowpart[8];
#pragma unroll
    for (int i = 0; i < 8; i++) rowpart[i] = 0.f;

    for (int et = 0; et < 8; ++et) {
        const int n0 = et * BN;

        unsigned long long accp[8][4];
#pragma unroll
        for (int i = 0; i < 8; i++)
#pragma unroll
            for (int j = 0; j < 4; j++) accp[i][j] = 0ull;

        for (int k0 = 0; k0 < DIM; k0 += BK) {
            float4 a0 = *(const float4*)&enc[(size_t)(row0 + lr) * DIM + k0 + lc];
            float4 a1 = *(const float4*)&enc[(size_t)(row0 + lr + 64) * DIM + k0 + lc];
            float4 b0 = *(const float4*)&Wh[(size_t)(n0 + lr) * DIM + k0 + lc];
            float4 b1 = *(const float4*)&Wh[(size_t)(n0 + lr + 64) * DIM + k0 + lc];

            __syncthreads();   // previous tile fully consumed
            As[lc + 0][lr] = a0.x; As[lc + 1][lr] = a0.y;
            As[lc + 2][lr] = a0.z; As[lc + 3][lr] = a0.w;
            As[lc + 0][lr + 64] = a1.x; As[lc + 1][lr + 64] = a1.y;
            As[lc + 2][lr + 64] = a1.z; As[lc + 3][lr + 64] = a1.w;
            Bs[lc + 0][lr] = b0.x; Bs[lc + 1][lr] = b0.y;
            Bs[lc + 2][lr] = b0.z; Bs[lc + 3][lr] = b0.w;
            Bs[lc + 0][lr + 64] = b1.x; Bs[lc + 1][lr + 64] = b1.y;
            Bs[lc + 2][lr + 64] = b1.z; Bs[lc + 3][lr + 64] = b1.w;
            __syncthreads();

#pragma unroll
            for (int k = 0; k < BK; k++) {
                const float4 m0 = *(const float4*)&As[k][ty * 8];
                const float4 m1 = *(const float4*)&As[k][ty * 8 + 4];
                const ulonglong2 nb0 = *(const ulonglong2*)&Bs[k][tx * 8];
                const ulonglong2 nb1 = *(const ulonglong2*)&Bs[k][tx * 8 + 4];
                unsigned long long np[4] = {nb0.x, nb0.y, nb1.x, nb1.y};
                float mv[8] = {m0.x, m0.y, m0.z, m0.w, m1.x, m1.y, m1.z, m1.w};
#pragma unroll
                for (int i = 0; i < 8; i++) {
                    const unsigned long long mm = dup2(mv[i]);
#pragma unroll
                    for (int j = 0; j < 4; j++)
                        fma2(accp[i][j], mm, np[j]);
                }
            }
        }

        // fused epilogue: x = acc + dec + cov*wc ; rowpart += v * tanh(x)
        const int ebase = n0 + tx * 8;
        float dv[8], wcv[8], vv[8];
#pragma unroll
        for (int j = 0; j < 8; j++) {
            dv[j]  = g_dec[b * DIM + ebase + j];
            wcv[j] = wc[ebase + j];
            vv[j]  = v[ebase + j];
        }
#pragma unroll
        for (int i = 0; i < 8; i++) {
            const float cv = cov[b * SEQ + sbase + i];
            float p = 0.f;
#pragma unroll
            for (int j = 0; j < 4; j++) {
                const float x0 = lo32(accp[i][j]) + dv[2 * j]     + cv * wcv[2 * j];
                const float x1 = hi32(accp[i][j]) + dv[2 * j + 1] + cv * wcv[2 * j + 1];
                p += vv[2 * j] * tanhf(x0) + vv[2 * j + 1] * tanhf(x1);
            }
            rowpart[i] += p;
        }
    }

    // reduce rowpart over the 16 tx-lanes (butterfly stays inside 16-lane group)
#pragma unroll
    for (int off = 8; off >= 1; off >>= 1)
#pragma unroll
        for (int i = 0; i < 8; i++)
            rowpart[i] += __shfl_xor_sync(0xffffffffu, rowpart[i], off);

    if (tx == 0) {
#pragma unroll
        for (int i = 0; i < 8; i++)
            g_score[row0 + ty * 8 + i] = rowpart[i];
    }
}

// ---------------------------------------------------------------------------
// K3: masked softmax over S + renormalize; writes aw and new_coverage.
// one block per batch row, 512 threads
// ---------------------------------------------------------------------------
__global__ void softmax_kernel(const float* __restrict__ mask,
                               const float* __restrict__ cov,
                               float* __restrict__ out) {
    __shared__ float red[SEQ];
    const int b = blockIdx.x;
    const int s = threadIdx.x;

    const float sc = g_score[b * SEQ + s];

    red[s] = sc;
    __syncthreads();
    for (int off = 256; off > 0; off >>= 1) {
        if (s < off) red[s] = fmaxf(red[s], red[s + off]);
        __syncthreads();
    }
    const float mx = red[0];
    __syncthreads();

    const float ex = expf(sc - mx);
    red[s] = ex;
    __syncthreads();
    for (int off = 256; off > 0; off >>= 1) {
        if (s < off) red[s] += red[s + off];
        __syncthreads();
    }
    const float sum = red[0];
    __syncthreads();

    const float aw0 = (ex / sum) * mask[b * SEQ + s];
    red[s] = aw0;
    __syncthreads();
    for (int off = 256; off > 0; off >>= 1) {
        if (s < off) red[s] += red[s + off];
        __syncthreads();
    }
    const float sum2 = red[0];

    const float aw = aw0 / sum2;
    // output layout: [context (B*D) | aw (B*S) | new_coverage (B*S)]
    out[BATCH * DIM + b * SEQ + s] = aw;
    out[BATCH * DIM + BATCH * SEQ + b * SEQ + s] = cov[b * SEQ + s] + aw;
}

// ---------------------------------------------------------------------------
// K4: context[b,d] = sum_s aw[b,s] * enc[b,s,d]   (memory-bound, 268 MB stream)
// one block per batch, 1024 threads (thread = d), coalesced enc reads
// ---------------------------------------------------------------------------
__global__ void context_kernel(const float* __restrict__ enc,
                               const float* __restrict__ aw,
                               float* __restrict__ outc) {
    __shared__ float aws[SEQ];
    const int b = blockIdx.x;
    for (int s = threadIdx.x; s < SEQ; s += blockDim.x)
        aws[s] = aw[b * SEQ + s];
    __syncthreads();

    const int d = threadIdx.x;
    const float* ebase = enc + (size_t)b * SEQ * DIM + d;
    float acc = 0.f;
#pragma unroll 8
    for (int s = 0; s < SEQ; s++)
        acc = fmaf(aws[s], ebase[(size_t)s * DIM], acc);
    outc[b * DIM + d] = acc;
}

// ---------------------------------------------------------------------------
extern "C" void kernel_launch(void* const* d_in, const int* in_sizes, int n_in,
                              void* d_out, int out_size) {
    const float* h_dec = (const float*)d_in[0];  // (1,B,H)
    const float* c_dec = (const float*)d_in[1];  // (1,B,H)
    const float* enc   = (const float*)d_in[2];  // (B,S,D)
    const float* mask  = (const float*)d_in[3];  // (B,S)
    const float* cov   = (const float*)d_in[4];  // (B,S)
    const float* Wh    = (const float*)d_in[5];  // (D,D)
    const float* Ws    = (const float*)d_in[6];  // (D,D)
    const float* Wsb   = (const float*)d_in[7];  // (D,)
    const float* v     = (const float*)d_in[8];  // (D,)
    const float* wc    = (const float*)d_in[9];  // (D,)
    float* out = (float*)d_out;

    dec_feat_kernel<<<dim3(8, BATCH), 128>>>(h_dec, c_dec, Ws, Wsb);
    score_kernel<<<MROWS / BM, 256>>>(enc, Wh, cov, v, wc);
    softmax_kernel<<<BATCH, SEQ>>>(mask, cov, out);
    context_kernel<<<BATCH, DIM>>>(enc, out + BATCH * DIM, out);
}